// round 1
// baseline (speedup 1.0000x reference)
#include <cuda_runtime.h>

#define BATCH 8
#define NA 76725
#define NC 80
#define KC 256
#define CAP 4096
#define MAXT 200
#define BC (BATCH*NC)        // 640
#define NFLAT (NC*KC)        // 20480
#define TFILT 2.0f

// ---------------- scratch (device globals; no allocations) ----------------
__device__ int    g_cnt[BC];
__device__ float  g_cval[BC*CAP];
__device__ int    g_cidx[BC*CAP];
__device__ float  g_tsc [BC*KC];     // sigmoid score of candidate, sorted desc
__device__ int    g_tanc[BC*KC];     // anchor index of candidate
__device__ float  g_sel [BC*KC];     // kept ? sigmoid : -1
__device__ float4 g_box4[BC*KC];     // decoded corners per candidate

// ---------------- exact-rounding helpers (match XLA per-HLO rounding) -----
__device__ __forceinline__ float mulrn(float a, float b){ return __fmul_rn(a,b); }
__device__ __forceinline__ float addrn(float a, float b){ return __fadd_rn(a,b); }
__device__ __forceinline__ float subrn(float a, float b){ return __fsub_rn(a,b); }

// XLA f32 tanh rational approximation (elemental_ir_emitter), no FMA fusion.
__device__ __forceinline__ float xla_tanh(float x){
    float ax = fabsf(x);
    if (ax < 0.0004f) return x;
    float cx = fminf(fmaxf(x, -7.90531110763549805f), 7.90531110763549805f);
    float s = mulrn(cx, cx);
    float p = -2.76076847742355e-16f;
    p = addrn(mulrn(p, s),  2.00018790482477e-13f);
    p = addrn(mulrn(p, s), -8.60467152213735e-11f);
    p = addrn(mulrn(p, s),  5.12229709037114e-08f);
    p = addrn(mulrn(p, s),  1.48572235717979e-05f);
    p = addrn(mulrn(p, s),  6.37261928875436e-04f);
    p = addrn(mulrn(p, s),  4.89352455891786e-03f);
    p = mulrn(cx, p);
    float q = 1.19825839466702e-06f;
    q = addrn(mulrn(q, s), 1.18534705686654e-04f);
    q = addrn(mulrn(q, s), 2.26843463243900e-03f);
    q = addrn(mulrn(q, s), 4.89352518554385e-03f);
    return __fdiv_rn(p, q);
}
__device__ __forceinline__ float xla_sigmoid(float x){
    return addrn(0.5f, mulrn(0.5f, xla_tanh(mulrn(0.5f, x))));
}

// key = (sigmoid_bits << 32) | ~anchor   (sigmoid>0 so bit pattern is monotone)
__device__ __forceinline__ unsigned long long pack_key(float sig, unsigned int idx){
    return ((unsigned long long)__float_as_uint(sig) << 32) |
           (unsigned long long)(~idx);
}

// ---------------- K0: zero per-class counters ------------------------------
__global__ void k_zero(){
    int i = blockIdx.x*blockDim.x + threadIdx.x;
    if (i < BC) g_cnt[i] = 0;
}

// ---------------- K1: coalesced streaming filter on cls_pred ---------------
__global__ void k_filter(const float* __restrict__ cls){
    int gid = blockIdx.x*blockDim.x + threadIdx.x;
    const int n4 = (BATCH*NA*NC)/4;
    if (gid >= n4) return;
    float4 v = reinterpret_cast<const float4*>(cls)[gid];
    int e   = gid*4;
    int b   = e / (NA*NC);
    int rem = e - b*(NA*NC);
    int a   = rem / NC;
    int c0  = rem - a*NC;              // multiple of 4, so all 4 lanes share (b,a)
    float vals[4] = {v.x, v.y, v.z, v.w};
    #pragma unroll
    for (int k = 0; k < 4; k++){
        if (vals[k] > TFILT){
            int bc  = b*NC + c0 + k;
            int pos = atomicAdd(&g_cnt[bc], 1);
            if (pos < CAP){
                g_cval[bc*CAP + pos] = vals[k];
                g_cidx[bc*CAP + pos] = a;
            }
        }
    }
}

// ---------------- bitonic sort (descending) on shared u64 ------------------
__device__ __forceinline__ void bitonic_desc(unsigned long long* sk, int n, int tid, int bs){
    for (int k = 2; k <= n; k <<= 1){
        for (int j = k >> 1; j > 0; j >>= 1){
            for (int i = tid; i < n; i += bs){
                int ixj = i ^ j;
                if (ixj > i){
                    unsigned long long x = sk[i], y = sk[ixj];
                    bool swap = ((i & k) == 0) ? (x < y) : (x > y);
                    if (swap){ sk[i] = y; sk[ixj] = x; }
                }
            }
            __syncthreads();
        }
    }
}

// ---------------- K2: exact per-(b,c) top-256 by (sigmoid desc, idx asc) ---
__global__ void k_topk(const float* __restrict__ cls){
    __shared__ unsigned long long sk[CAP];
    int bc  = blockIdx.x;
    int tid = threadIdx.x;
    int cnt = g_cnt[bc];

    if (cnt >= KC && cnt <= CAP){
        for (int i = tid; i < CAP; i += 256){
            unsigned long long key = 0ULL;
            if (i < cnt){
                float sg = xla_sigmoid(g_cval[bc*CAP + i]);
                key = pack_key(sg, (unsigned int)g_cidx[bc*CAP + i]);
            }
            sk[i] = key;
        }
        __syncthreads();
        bitonic_desc(sk, CAP, tid, 256);
        if (tid < KC){
            unsigned long long key = sk[tid];
            g_tsc [bc*KC + tid] = __uint_as_float((unsigned int)(key >> 32));
            g_tanc[bc*KC + tid] = (int)(~(unsigned int)key);
        }
    } else {
        // Exact fallback: iterative max-extraction over the full column.
        // (Never triggers for N(0,1) inputs; correctness safety net only.)
        int b = bc / NC, c = bc - b*NC;
        const float* col = cls + (size_t)b*NA*NC + c;
        __shared__ unsigned long long red[256];
        unsigned long long cur = 0xFFFFFFFFFFFFFFFFULL;
        for (int r = 0; r < KC; r++){
            unsigned long long best = 0ULL;
            for (int a = tid; a < NA; a += 256){
                float sg = xla_sigmoid(col[(size_t)a*NC]);
                unsigned long long key = pack_key(sg, (unsigned int)a);
                if (key < cur && key > best) best = key;
            }
            red[tid] = best; __syncthreads();
            for (int s = 128; s > 0; s >>= 1){
                if (tid < s && red[tid+s] > red[tid]) red[tid] = red[tid+s];
                __syncthreads();
            }
            cur = red[0];
            if (tid == 0){
                g_tsc [bc*KC + r] = __uint_as_float((unsigned int)(cur >> 32));
                g_tanc[bc*KC + r] = (int)(~(unsigned int)cur);
            }
            __syncthreads();
        }
    }
}

// ---------------- K3: decode boxes + greedy NMS per (b,c) ------------------
__global__ void k_nms(const float* __restrict__ bpred, const float* __restrict__ anch){
    __shared__ float4 sbox[KC];
    __shared__ unsigned int smask[KC*8];
    __shared__ unsigned int selig[8];
    __shared__ unsigned int skeep[8];
    int bc  = blockIdx.x;
    int tid = threadIdx.x;
    int b   = bc / NC;

    int   a  = g_tanc[bc*KC + tid];
    float sc = g_tsc [bc*KC + tid];

    float4 bp = reinterpret_cast<const float4*>(bpred)[(size_t)b*NA + a];
    float4 an = reinterpret_cast<const float4*>(anch)[a];

    // decode (match jnp op-by-op rounding, no FMA)
    float dx = mulrn(bp.x, 0.1f), dy = mulrn(bp.y, 0.1f);
    float dw = mulrn(bp.z, 0.2f), dh = mulrn(bp.w, 0.2f);
    float cx = addrn(mulrn(dx, an.z), an.x);
    float cy = addrn(mulrn(dy, an.w), an.y);
    float w  = mulrn(expf(dw), an.z);
    float h  = mulrn(expf(dh), an.w);
    float4 box;
    box.x = subrn(cx, mulrn(0.5f, w));
    box.y = subrn(cy, mulrn(0.5f, h));
    box.z = addrn(cx, mulrn(0.5f, w));
    box.w = addrn(cy, mulrn(0.5f, h));
    sbox[tid] = box;
    g_box4[bc*KC + tid] = box;

    // eligibility (sigmoid > 0.5)
    unsigned int bal = __ballot_sync(0xFFFFFFFFu, sc > 0.5f);
    if ((tid & 31) == 0) selig[tid >> 5] = bal;
    __syncthreads();

    // suppression mask: bit j (j > tid) set if IoU(tid, j) > 0.5
    float a1 = mulrn(subrn(box.z, box.x), subrn(box.w, box.y));
    unsigned int m[8] = {0,0,0,0,0,0,0,0};
    for (int j = tid + 1; j < KC; j++){
        float4 o   = sbox[j];
        float ltx  = fmaxf(box.x, o.x), lty = fmaxf(box.y, o.y);
        float rbx  = fminf(box.z, o.z), rby = fminf(box.w, o.w);
        float iw   = fmaxf(subrn(rbx, ltx), 0.0f);
        float ih   = fmaxf(subrn(rby, lty), 0.0f);
        float inter= mulrn(iw, ih);
        float a2   = mulrn(subrn(o.z, o.x), subrn(o.w, o.y));
        float un   = fmaxf(subrn(addrn(a1, a2), inter), 1e-8f);
        if (__fdiv_rn(inter, un) > 0.5f) m[j >> 5] |= 1u << (j & 31);
    }
    #pragma unroll
    for (int w8 = 0; w8 < 8; w8++) smask[tid*8 + w8] = m[w8];
    __syncthreads();

    if (tid == 0){
        unsigned int keep[8];
        #pragma unroll
        for (int w8 = 0; w8 < 8; w8++) keep[w8] = selig[w8];
        // greedy suppression (full pass, cap applied after — matches reference)
        for (int i = 0; i < KC; i++){
            if ((keep[i >> 5] >> (i & 31)) & 1u){
                const unsigned int* mi = &smask[i*8];
                #pragma unroll
                for (int w8 = 0; w8 < 8; w8++) keep[w8] &= ~mi[w8];
            }
        }
        // cap: first MAXT kept survive
        int cnt = 0;
        #pragma unroll
        for (int w8 = 0; w8 < 8; w8++){
            unsigned int kk = keep[w8];
            if (cnt >= MAXT){ kk = 0u; }
            else {
                int pc = __popc(kk);
                if (cnt + pc > MAXT){
                    int need = MAXT - cnt;
                    unsigned int outw = 0u;
                    for (int bit = 0; bit < 32 && need > 0; bit++){
                        if ((kk >> bit) & 1u){ outw |= 1u << bit; need--; }
                    }
                    kk = outw;
                }
            }
            cnt += __popc(kk);
            skeep[w8] = kk;
        }
    }
    __syncthreads();
    unsigned int kw = skeep[tid >> 5];
    g_sel[bc*KC + tid] = ((kw >> (tid & 31)) & 1u) ? sc : -1.0f;
}

// ---------------- K4: per-batch global top-200 + output --------------------
__device__ __forceinline__ unsigned int flip_bits(unsigned int u){
    return u ^ ((u >> 31) ? 0xFFFFFFFFu : 0x80000000u);
}

__global__ void k_final(float* __restrict__ out){
    __shared__ unsigned int hist[256];
    __shared__ unsigned long long list[512];
    __shared__ int s_cnt;
    __shared__ int s_bin, s_above;
    int b   = blockIdx.x;
    int tid = threadIdx.x;
    const float* sel = g_sel + b*NFLAT;

    // radix-select the MAXT-th largest flipped key
    unsigned int prefix = 0;
    int remaining = MAXT;
    for (int shift = 24; shift >= 0; shift -= 8){
        hist[tid] = 0u;
        __syncthreads();
        for (int i = tid; i < NFLAT; i += 256){
            unsigned int fk = flip_bits(__float_as_uint(sel[i]));
            bool match = (shift == 24) || ((fk >> (shift + 8)) == prefix);
            if (match) atomicAdd(&hist[(fk >> shift) & 0xFFu], 1u);
        }
        __syncthreads();
        if (tid == 0){
            int cum = 0, bin = 255;
            for (; bin >= 0; bin--){
                cum += (int)hist[bin];
                if (cum >= remaining) break;
            }
            s_bin = bin;
            s_above = cum - (int)hist[bin];
        }
        __syncthreads();
        prefix = (prefix << 8) | (unsigned int)s_bin;
        remaining -= s_above;
        __syncthreads();
    }

    // collect all entries >= threshold (ties included), packed with ~flat_idx
    if (tid == 0) s_cnt = 0;
    __syncthreads();
    for (int i = tid; i < NFLAT; i += 256){
        unsigned int fk = flip_bits(__float_as_uint(sel[i]));
        if (fk >= prefix){
            int pos = atomicAdd(&s_cnt, 1);
            if (pos < 512)
                list[pos] = ((unsigned long long)fk << 32) |
                            (unsigned long long)(~(unsigned int)i);
        }
    }
    __syncthreads();
    int m = s_cnt < 512 ? s_cnt : 512;
    for (int i = tid; i < 512; i += 256) if (i >= m) list[i] = 0ULL;
    __syncthreads();
    bitonic_desc(list, 512, tid, 256);

    if (tid < MAXT){
        unsigned long long key = list[tid];
        unsigned int fk = (unsigned int)(key >> 32);
        unsigned int u  = (fk & 0x80000000u) ? (fk ^ 0x80000000u) : ~fk;
        float scv = __uint_as_float(u);
        int flat  = (int)(~(unsigned int)key);

        float4 bx = make_float4(0.f, 0.f, 0.f, 0.f);
        float  so = 0.f, lab = -1.f;
        if (scv > 0.0f && flat >= 0 && flat < NFLAT){
            int c    = flat >> 8;
            int slot = flat & 255;
            bx  = g_box4[(b*NC + c)*KC + slot];
            so  = scv;
            lab = (float)c;
        }
        float* ob = out;                       // [B, MAXT, 4]
        float* os = out + BATCH*MAXT*4;        // [B, MAXT]
        float* ol = out + BATCH*MAXT*5;        // [B, MAXT]
        reinterpret_cast<float4*>(ob)[b*MAXT + tid] = bx;
        os[b*MAXT + tid] = so;
        ol[b*MAXT + tid] = lab;
    }
}

// ---------------- launch ----------------------------------------------------
extern "C" void kernel_launch(void* const* d_in, const int* in_sizes, int n_in,
                              void* d_out, int out_size){
    const float* box_pred = (const float*)d_in[0];   // [B, A, 4]
    const float* cls_pred = (const float*)d_in[1];   // [B, A, C]
    const float* anchors  = (const float*)d_in[2];   // [A, 4]
    float* out = (float*)d_out;

    k_zero<<<(BC + 255)/256, 256>>>();
    int n4 = (BATCH*NA*NC)/4;
    k_filter<<<(n4 + 255)/256, 256>>>(cls_pred);
    k_topk<<<BC, 256>>>(cls_pred);
    k_nms<<<BC, 256>>>(box_pred, anchors);
    k_final<<<BATCH, 256>>>(out);
}

// round 2
// speedup vs baseline: 1.2262x; 1.2262x over previous
#include <cuda_runtime.h>

#define BATCH 8
#define NA 76725
#define NC 80
#define KC 256
#define CAP 4096
#define MAXT 200
#define BC (BATCH*NC)        // 640
#define NFLAT (NC*KC)        // 20480
#define TFILT 2.0f
#define COLBUF 1024

// ---------------- scratch (device globals; no allocations) ----------------
__device__ int    g_cnt[BC];
__device__ float  g_cval[BC*CAP];
__device__ int    g_cidx[BC*CAP];
__device__ float  g_tsc [BC*KC];     // sigmoid score of candidate, sorted desc
__device__ int    g_tanc[BC*KC];     // anchor index of candidate
__device__ float  g_sel [BC*KC];     // kept ? sigmoid : -1
__device__ float4 g_box4[BC*KC];     // decoded corners per candidate

// ---------------- exact-rounding helpers (match XLA per-HLO rounding) -----
__device__ __forceinline__ float mulrn(float a, float b){ return __fmul_rn(a,b); }
__device__ __forceinline__ float addrn(float a, float b){ return __fadd_rn(a,b); }
__device__ __forceinline__ float subrn(float a, float b){ return __fsub_rn(a,b); }

// XLA f32 tanh rational approximation (elemental_ir_emitter), no FMA fusion.
__device__ __forceinline__ float xla_tanh(float x){
    float ax = fabsf(x);
    if (ax < 0.0004f) return x;
    float cx = fminf(fmaxf(x, -7.90531110763549805f), 7.90531110763549805f);
    float s = mulrn(cx, cx);
    float p = -2.76076847742355e-16f;
    p = addrn(mulrn(p, s),  2.00018790482477e-13f);
    p = addrn(mulrn(p, s), -8.60467152213735e-11f);
    p = addrn(mulrn(p, s),  5.12229709037114e-08f);
    p = addrn(mulrn(p, s),  1.48572235717979e-05f);
    p = addrn(mulrn(p, s),  6.37261928875436e-04f);
    p = addrn(mulrn(p, s),  4.89352455891786e-03f);
    p = mulrn(cx, p);
    float q = 1.19825839466702e-06f;
    q = addrn(mulrn(q, s), 1.18534705686654e-04f);
    q = addrn(mulrn(q, s), 2.26843463243900e-03f);
    q = addrn(mulrn(q, s), 4.89352518554385e-03f);
    return __fdiv_rn(p, q);
}
__device__ __forceinline__ float xla_sigmoid(float x){
    return addrn(0.5f, mulrn(0.5f, xla_tanh(mulrn(0.5f, x))));
}

// key = (sigmoid_bits << 32) | ~anchor   (sigmoid>0 so bit pattern is monotone)
__device__ __forceinline__ unsigned long long pack_key(float sig, unsigned int idx){
    return ((unsigned long long)__float_as_uint(sig) << 32) |
           (unsigned long long)(~idx);
}

// ---------------- K0: zero per-class counters ------------------------------
__global__ void k_zero(){
    int i = blockIdx.x*blockDim.x + threadIdx.x;
    if (i < BC) g_cnt[i] = 0;
}

// ---------------- K1: coalesced streaming filter on cls_pred ---------------
__global__ void k_filter(const float* __restrict__ cls){
    int gid = blockIdx.x*blockDim.x + threadIdx.x;
    const int n4 = (BATCH*NA*NC)/4;
    if (gid >= n4) return;
    float4 v = reinterpret_cast<const float4*>(cls)[gid];
    int e   = gid*4;
    int b   = e / (NA*NC);
    int rem = e - b*(NA*NC);
    int a   = rem / NC;
    int c0  = rem - a*NC;              // multiple of 4, so all 4 lanes share (b,a)
    float vals[4] = {v.x, v.y, v.z, v.w};
    #pragma unroll
    for (int k = 0; k < 4; k++){
        if (vals[k] > TFILT){
            int bc  = b*NC + c0 + k;
            int pos = atomicAdd(&g_cnt[bc], 1);
            if (pos < CAP){
                g_cval[bc*CAP + pos] = vals[k];
                g_cidx[bc*CAP + pos] = a;
            }
        }
    }
}

// ---------------- bitonic sort (descending) on shared u64 ------------------
__device__ __forceinline__ void bitonic_desc(unsigned long long* sk, int n, int tid, int bs){
    for (int k = 2; k <= n; k <<= 1){
        for (int j = k >> 1; j > 0; j >>= 1){
            for (int i = tid; i < n; i += bs){
                int ixj = i ^ j;
                if (ixj > i){
                    unsigned long long x = sk[i], y = sk[ixj];
                    bool swap = ((i & k) == 0) ? (x < y) : (x > y);
                    if (swap){ sk[i] = y; sk[ixj] = x; }
                }
            }
            __syncthreads();
        }
    }
}

// exact fallback: iterative max-extraction over the full logit column
__device__ void topk_fallback(const float* __restrict__ cls, int bc, int tid){
    int b = bc / NC, c = bc - b*NC;
    const float* col = cls + (size_t)b*NA*NC + c;
    __shared__ unsigned long long red[256];
    unsigned long long cur = 0xFFFFFFFFFFFFFFFFULL;
    for (int r = 0; r < KC; r++){
        unsigned long long best = 0ULL;
        for (int a = tid; a < NA; a += 256){
            float sg = xla_sigmoid(col[(size_t)a*NC]);
            unsigned long long key = pack_key(sg, (unsigned int)a);
            if (key < cur && key > best) best = key;
        }
        red[tid] = best; __syncthreads();
        for (int s = 128; s > 0; s >>= 1){
            if (tid < s && red[tid+s] > red[tid]) red[tid] = red[tid+s];
            __syncthreads();
        }
        cur = red[0];
        if (tid == 0){
            g_tsc [bc*KC + r] = __uint_as_float((unsigned int)(cur >> 32));
            g_tanc[bc*KC + r] = (int)(~(unsigned int)cur);
        }
        __syncthreads();
    }
}

// ---------------- K2: exact per-(b,c) top-256 via radix select --------------
__global__ __launch_bounds__(256) void k_topk(const float* __restrict__ cls){
    __shared__ unsigned int ssig[CAP];
    __shared__ unsigned int sidx[CAP];
    __shared__ unsigned long long keys[COLBUF];
    __shared__ unsigned int hist[256];
    __shared__ int s_bin, s_above, s_cnt;
    int bc  = blockIdx.x;
    int tid = threadIdx.x;
    int cnt = g_cnt[bc];

    bool ok = (cnt >= KC && cnt <= CAP);
    if (ok){
        // load candidates, compute sigmoid once
        for (int i = tid; i < cnt; i += 256){
            float sg = xla_sigmoid(g_cval[bc*CAP + i]);
            ssig[i] = __float_as_uint(sg);     // positive -> bit-monotone
            sidx[i] = (unsigned int)g_cidx[bc*CAP + i];
        }
        __syncthreads();

        // radix-select (descending) the full 32-bit value at rank KC
        unsigned int prefix = 0; int remaining = KC;
        for (int shift = 24; shift >= 0; shift -= 8){
            hist[tid] = 0u; __syncthreads();
            for (int i = tid; i < cnt; i += 256){
                unsigned int u = ssig[i];
                if (shift == 24 || (u >> (shift + 8)) == prefix)
                    atomicAdd(&hist[(u >> shift) & 0xFFu], 1u);
            }
            __syncthreads();
            if (tid == 0){
                int cum = 0, bin = 255;
                for (; bin >= 0; bin--){ cum += (int)hist[bin]; if (cum >= remaining) break; }
                s_bin = bin; s_above = cum - (int)hist[bin];
            }
            __syncthreads();
            prefix = (prefix << 8) | (unsigned int)s_bin;
            remaining -= s_above;
            __syncthreads();
        }

        // collect all entries with sig >= s* (includes tie bucket)
        if (tid == 0) s_cnt = 0;
        __syncthreads();
        for (int i = tid; i < cnt; i += 256){
            unsigned int u = ssig[i];
            if (u >= prefix){
                int p = atomicAdd(&s_cnt, 1);
                if (p < COLBUF)
                    keys[p] = ((unsigned long long)u << 32) |
                              (unsigned long long)(~sidx[i]);
            }
        }
        __syncthreads();
        int m = s_cnt;
        if (m <= COLBUF){
            for (int i = tid; i < COLBUF; i += 256) if (i >= m) keys[i] = 0ULL;
            __syncthreads();
            bitonic_desc(keys, COLBUF, tid, 256);
            if (tid < KC){
                unsigned long long key = keys[tid];
                g_tsc [bc*KC + tid] = __uint_as_float((unsigned int)(key >> 32));
                g_tanc[bc*KC + tid] = (int)(~(unsigned int)key);
            }
        } else {
            ok = false;          // pathological tie explosion -> exact fallback
        }
        __syncthreads();
    }
    if (!ok) topk_fallback(cls, bc, tid);
}

// ---------------- K3: decode boxes + greedy NMS per (b,c) ------------------
__global__ __launch_bounds__(256) void k_nms(const float* __restrict__ bpred,
                                             const float* __restrict__ anch){
    __shared__ float4 sbox[KC];
    __shared__ float  sarea[KC];
    __shared__ unsigned int smask[KC*8];
    __shared__ unsigned int selig[8];
    __shared__ unsigned int skeep[8];
    int bc  = blockIdx.x;
    int tid = threadIdx.x;
    int b   = bc / NC;

    int   a  = g_tanc[bc*KC + tid];
    float sc = g_tsc [bc*KC + tid];

    float4 bp = reinterpret_cast<const float4*>(bpred)[(size_t)b*NA + a];
    float4 an = reinterpret_cast<const float4*>(anch)[a];

    // decode (match jnp op-by-op rounding, no FMA)
    float dx = mulrn(bp.x, 0.1f), dy = mulrn(bp.y, 0.1f);
    float dw = mulrn(bp.z, 0.2f), dh = mulrn(bp.w, 0.2f);
    float cx = addrn(mulrn(dx, an.z), an.x);
    float cy = addrn(mulrn(dy, an.w), an.y);
    float w  = mulrn(expf(dw), an.z);
    float h  = mulrn(expf(dh), an.w);
    float4 box;
    box.x = subrn(cx, mulrn(0.5f, w));
    box.y = subrn(cy, mulrn(0.5f, h));
    box.z = addrn(cx, mulrn(0.5f, w));
    box.w = addrn(cy, mulrn(0.5f, h));
    sbox[tid]  = box;
    sarea[tid] = mulrn(subrn(box.z, box.x), subrn(box.w, box.y));
    g_box4[bc*KC + tid] = box;

    // zero suppression masks
    #pragma unroll
    for (int w8 = 0; w8 < 8; w8++) smask[tid*8 + w8] = 0u;

    // eligibility (sigmoid > 0.5)
    unsigned int bal = __ballot_sync(0xFFFFFFFFu, sc > 0.5f);
    if ((tid & 31) == 0) selig[tid >> 5] = bal;
    __syncthreads();

    // balanced round-robin pair enumeration: each unordered pair exactly once.
    // d = 1..127: pair (t, t+d mod 256) owned by t; d = 128 owned by t < 128.
    float a1 = sarea[tid];
    int dmax = (tid < 128) ? 128 : 127;
    for (int d = 1; d <= dmax; d++){
        int j = (tid + d) & 255;
        float4 o   = sbox[j];
        float ltx  = fmaxf(box.x, o.x), lty = fmaxf(box.y, o.y);
        float rbx  = fminf(box.z, o.z), rby = fminf(box.w, o.w);
        float iw   = fmaxf(subrn(rbx, ltx), 0.0f);
        float ih   = fmaxf(subrn(rby, lty), 0.0f);
        float inter= mulrn(iw, ih);
        float un   = fmaxf(subrn(addrn(a1, sarea[j]), inter), 1e-8f);
        if (__fdiv_rn(inter, un) > 0.5f){
            int lo = tid < j ? tid : j;
            int hi = tid < j ? j : tid;
            atomicOr(&smask[lo*8 + (hi >> 5)], 1u << (hi & 31));
        }
    }
    __syncthreads();

    if (tid == 0){
        unsigned int keep[8];
        #pragma unroll
        for (int w8 = 0; w8 < 8; w8++) keep[w8] = selig[w8];
        // greedy suppression (full pass, cap applied after — matches reference)
        for (int i = 0; i < KC; i++){
            if ((keep[i >> 5] >> (i & 31)) & 1u){
                const unsigned int* mi = &smask[i*8];
                #pragma unroll
                for (int w8 = 0; w8 < 8; w8++) keep[w8] &= ~mi[w8];
            }
        }
        // cap: first MAXT kept survive
        int cnt = 0;
        #pragma unroll
        for (int w8 = 0; w8 < 8; w8++){
            unsigned int kk = keep[w8];
            if (cnt >= MAXT){ kk = 0u; }
            else {
                int pc = __popc(kk);
                if (cnt + pc > MAXT){
                    int need = MAXT - cnt;
                    unsigned int outw = 0u;
                    for (int bit = 0; bit < 32 && need > 0; bit++){
                        if ((kk >> bit) & 1u){ outw |= 1u << bit; need--; }
                    }
                    kk = outw;
                }
            }
            cnt += __popc(kk);
            skeep[w8] = kk;
        }
    }
    __syncthreads();
    unsigned int kw = skeep[tid >> 5];
    g_sel[bc*KC + tid] = ((kw >> (tid & 31)) & 1u) ? sc : -1.0f;
}

// ---------------- K4: per-batch global top-200 + output --------------------
__device__ __forceinline__ unsigned int flip_bits(unsigned int u){
    return u ^ ((u >> 31) ? 0xFFFFFFFFu : 0x80000000u);
}

__global__ void k_final(float* __restrict__ out){
    __shared__ unsigned int hist[256];
    __shared__ unsigned long long list[512];
    __shared__ int s_cnt;
    __shared__ int s_bin, s_above;
    int b   = blockIdx.x;
    int tid = threadIdx.x;
    const float* sel = g_sel + b*NFLAT;

    // radix-select the MAXT-th largest flipped key
    unsigned int prefix = 0;
    int remaining = MAXT;
    for (int shift = 24; shift >= 0; shift -= 8){
        hist[tid] = 0u;
        __syncthreads();
        for (int i = tid; i < NFLAT; i += 256){
            unsigned int fk = flip_bits(__float_as_uint(sel[i]));
            bool match = (shift == 24) || ((fk >> (shift + 8)) == prefix);
            if (match) atomicAdd(&hist[(fk >> shift) & 0xFFu], 1u);
        }
        __syncthreads();
        if (tid == 0){
            int cum = 0, bin = 255;
            for (; bin >= 0; bin--){
                cum += (int)hist[bin];
                if (cum >= remaining) break;
            }
            s_bin = bin;
            s_above = cum - (int)hist[bin];
        }
        __syncthreads();
        prefix = (prefix << 8) | (unsigned int)s_bin;
        remaining -= s_above;
        __syncthreads();
    }

    // collect all entries >= threshold (ties included), packed with ~flat_idx
    if (tid == 0) s_cnt = 0;
    __syncthreads();
    for (int i = tid; i < NFLAT; i += 256){
        unsigned int fk = flip_bits(__float_as_uint(sel[i]));
        if (fk >= prefix){
            int pos = atomicAdd(&s_cnt, 1);
            if (pos < 512)
                list[pos] = ((unsigned long long)fk << 32) |
                            (unsigned long long)(~(unsigned int)i);
        }
    }
    __syncthreads();
    int m = s_cnt < 512 ? s_cnt : 512;
    for (int i = tid; i < 512; i += 256) if (i >= m) list[i] = 0ULL;
    __syncthreads();
    bitonic_desc(list, 512, tid, 256);

    if (tid < MAXT){
        unsigned long long key = list[tid];
        unsigned int fk = (unsigned int)(key >> 32);
        unsigned int u  = (fk & 0x80000000u) ? (fk ^ 0x80000000u) : ~fk;
        float scv = __uint_as_float(u);
        int flat  = (int)(~(unsigned int)key);

        float4 bx = make_float4(0.f, 0.f, 0.f, 0.f);
        float  so = 0.f, lab = -1.f;
        if (scv > 0.0f && flat >= 0 && flat < NFLAT){
            int c    = flat >> 8;
            int slot = flat & 255;
            bx  = g_box4[(b*NC + c)*KC + slot];
            so  = scv;
            lab = (float)c;
        }
        float* ob = out;                       // [B, MAXT, 4]
        float* os = out + BATCH*MAXT*4;        // [B, MAXT]
        float* ol = out + BATCH*MAXT*5;        // [B, MAXT]
        reinterpret_cast<float4*>(ob)[b*MAXT + tid] = bx;
        os[b*MAXT + tid] = so;
        ol[b*MAXT + tid] = lab;
    }
}

// ---------------- launch ----------------------------------------------------
extern "C" void kernel_launch(void* const* d_in, const int* in_sizes, int n_in,
                              void* d_out, int out_size){
    const float* box_pred = (const float*)d_in[0];   // [B, A, 4]
    const float* cls_pred = (const float*)d_in[1];   // [B, A, C]
    const float* anchors  = (const float*)d_in[2];   // [A, 4]
    float* out = (float*)d_out;

    k_zero<<<(BC + 255)/256, 256>>>();
    int n4 = (BATCH*NA*NC)/4;
    k_filter<<<(n4 + 255)/256, 256>>>(cls_pred);
    k_topk<<<BC, 256>>>(cls_pred);
    k_nms<<<BC, 256>>>(box_pred, anchors);
    k_final<<<BATCH, 256>>>(out);
}

// round 3
// speedup vs baseline: 3.5122x; 2.8642x over previous
#include <cuda_runtime.h>

#define BATCH 8
#define NA 76725
#define NC 80
#define KC 256
#define CAP 4096
#define MAXT 200
#define BC (BATCH*NC)        // 640
#define NFLAT (NC*KC)        // 20480
#define TFILT 2.0f
#define COLBUF 1024

// k_filter tiling
#define FBLK 256
#define F4PT 24
#define CHUNK (FBLK*F4PT)            // 6144 float4 per block
#define N4B (NA*NC/4)                // 1,534,500 float4 per batch
#define BPB ((N4B + CHUNK - 1)/CHUNK) // 250
#define STAGE 2048

// ---------------- scratch (device globals; no allocations) ----------------
__device__ int    g_cnt[BC];
__device__ unsigned long long g_cand[(size_t)BC*CAP]; // (logit_bits<<32)|anchor
__device__ float  g_tsc [BC*KC];     // sigmoid score, sorted desc
__device__ int    g_tanc[BC*KC];     // anchor index
__device__ float  g_sel [BC*KC];     // kept ? sigmoid : -1
__device__ float4 g_box4[BC*KC];     // decoded corners

// ---------------- exact-rounding helpers ----------------------------------
__device__ __forceinline__ float mulrn(float a, float b){ return __fmul_rn(a,b); }
__device__ __forceinline__ float addrn(float a, float b){ return __fadd_rn(a,b); }
__device__ __forceinline__ float subrn(float a, float b){ return __fsub_rn(a,b); }

// XLA f32 tanh rational approximation, no FMA fusion.
__device__ __forceinline__ float xla_tanh(float x){
    float ax = fabsf(x);
    if (ax < 0.0004f) return x;
    float cx = fminf(fmaxf(x, -7.90531110763549805f), 7.90531110763549805f);
    float s = mulrn(cx, cx);
    float p = -2.76076847742355e-16f;
    p = addrn(mulrn(p, s),  2.00018790482477e-13f);
    p = addrn(mulrn(p, s), -8.60467152213735e-11f);
    p = addrn(mulrn(p, s),  5.12229709037114e-08f);
    p = addrn(mulrn(p, s),  1.48572235717979e-05f);
    p = addrn(mulrn(p, s),  6.37261928875436e-04f);
    p = addrn(mulrn(p, s),  4.89352455891786e-03f);
    p = mulrn(cx, p);
    float q = 1.19825839466702e-06f;
    q = addrn(mulrn(q, s), 1.18534705686654e-04f);
    q = addrn(mulrn(q, s), 2.26843463243900e-03f);
    q = addrn(mulrn(q, s), 4.89352518554385e-03f);
    return __fdiv_rn(p, q);
}
__device__ __forceinline__ float xla_sigmoid(float x){
    return addrn(0.5f, mulrn(0.5f, xla_tanh(mulrn(0.5f, x))));
}

__device__ __forceinline__ unsigned long long pack_key(float sig, unsigned int idx){
    return ((unsigned long long)__float_as_uint(sig) << 32) |
           (unsigned long long)(~idx);
}

// ---------------- K0: zero per-class counters ------------------------------
__global__ void k_zero(){
    int i = blockIdx.x*blockDim.x + threadIdx.x;
    if (i < BC) g_cnt[i] = 0;
}

// ---------------- K1: block-aggregated streaming filter --------------------
__global__ __launch_bounds__(FBLK) void k_filter(const float* __restrict__ cls){
    __shared__ unsigned long long stage[STAGE];
    __shared__ int shist[NC];
    __shared__ int sbase[NC];
    __shared__ int scur [NC];
    __shared__ int scnt;
    int tid   = threadIdx.x;
    int b     = blockIdx.x / BPB;
    int chunk = blockIdx.x % BPB;

    for (int i = tid; i < NC; i += FBLK){ shist[i] = 0; scur[i] = 0; }
    if (tid == 0) scnt = 0;
    __syncthreads();

    const float4* src = reinterpret_cast<const float4*>(cls) + (size_t)b*N4B;
    int base4 = chunk*CHUNK;

    for (int k = 0; k < F4PT; k++){
        int i4 = base4 + k*FBLK + tid;
        if (i4 >= N4B) break;
        float4 v = src[i4];
        int e  = i4*4;
        int a  = e / NC;
        int c0 = e - a*NC;            // multiple of 4
        float vals[4] = {v.x, v.y, v.z, v.w};
        #pragma unroll
        for (int t = 0; t < 4; t++){
            if (vals[t] > TFILT){
                int c = c0 + t;
                int p = atomicAdd(&scnt, 1);
                unsigned long long pk =
                    ((unsigned long long)__float_as_uint(vals[t]) << 32) |
                    ((unsigned long long)(unsigned)a << 7) | (unsigned)c;
                if (p < STAGE){
                    stage[p] = pk;
                    atomicAdd(&shist[c], 1);
                } else {
                    // staging overflow: exact direct path
                    int bc  = b*NC + c;
                    int pos = atomicAdd(&g_cnt[bc], 1);
                    if (pos < CAP)
                        g_cand[(size_t)bc*CAP + pos] =
                            ((unsigned long long)__float_as_uint(vals[t]) << 32) |
                            (unsigned)a;
                }
            }
        }
    }
    __syncthreads();

    if (tid < NC){
        int n = shist[tid];
        if (n > 0) sbase[tid] = atomicAdd(&g_cnt[b*NC + tid], n);
    }
    __syncthreads();

    int m = scnt < STAGE ? scnt : STAGE;
    for (int i = tid; i < m; i += FBLK){
        unsigned long long s = stage[i];
        int c = (int)(s & 127u);
        unsigned int a = (unsigned int)((s >> 7) & 0x1FFFFu);
        unsigned int vb = (unsigned int)(s >> 32);
        int off = sbase[c] + atomicAdd(&scur[c], 1);
        if (off < CAP)
            g_cand[(size_t)(b*NC + c)*CAP + off] =
                ((unsigned long long)vb << 32) | a;
    }
}

// ---------------- bitonic sort (descending) on shared u64 ------------------
__device__ __forceinline__ void bitonic_desc(unsigned long long* sk, int n, int tid, int bs){
    for (int k = 2; k <= n; k <<= 1){
        for (int j = k >> 1; j > 0; j >>= 1){
            for (int i = tid; i < n; i += bs){
                int ixj = i ^ j;
                if (ixj > i){
                    unsigned long long x = sk[i], y = sk[ixj];
                    bool swap = ((i & k) == 0) ? (x < y) : (x > y);
                    if (swap){ sk[i] = y; sk[ixj] = x; }
                }
            }
            __syncthreads();
        }
    }
}

// exact fallback: iterative max-extraction over the full logit column
__device__ void topk_fallback(const float* __restrict__ cls, int bc, int tid){
    int b = bc / NC, c = bc - b*NC;
    const float* col = cls + (size_t)b*NA*NC + c;
    __shared__ unsigned long long red[256];
    unsigned long long cur = 0xFFFFFFFFFFFFFFFFULL;
    for (int r = 0; r < KC; r++){
        unsigned long long best = 0ULL;
        for (int a = tid; a < NA; a += 256){
            float sg = xla_sigmoid(col[(size_t)a*NC]);
            unsigned long long key = pack_key(sg, (unsigned int)a);
            if (key < cur && key > best) best = key;
        }
        red[tid] = best; __syncthreads();
        for (int s = 128; s > 0; s >>= 1){
            if (tid < s && red[tid+s] > red[tid]) red[tid] = red[tid+s];
            __syncthreads();
        }
        cur = red[0];
        if (tid == 0){
            g_tsc [bc*KC + r] = __uint_as_float((unsigned int)(cur >> 32));
            g_tanc[bc*KC + r] = (int)(~(unsigned int)cur);
        }
        __syncthreads();
    }
}

// ---------------- K2: exact per-(b,c) top-256 via radix select --------------
__global__ __launch_bounds__(256) void k_topk(const float* __restrict__ cls){
    __shared__ unsigned int ssig[CAP];
    __shared__ unsigned int sidx[CAP];
    __shared__ unsigned long long keys[COLBUF];
    __shared__ unsigned int hist[256];
    __shared__ int s_bin, s_above, s_cnt;
    int bc  = blockIdx.x;
    int tid = threadIdx.x;
    int cnt = g_cnt[bc];

    bool ok = (cnt >= KC && cnt <= CAP);
    if (ok){
        for (int i = tid; i < cnt; i += 256){
            unsigned long long cd = g_cand[(size_t)bc*CAP + i];
            float sg = xla_sigmoid(__uint_as_float((unsigned int)(cd >> 32)));
            ssig[i] = __float_as_uint(sg);
            sidx[i] = (unsigned int)(cd & 0xFFFFFFFFu);
        }
        __syncthreads();

        unsigned int prefix = 0; int remaining = KC;
        for (int shift = 24; shift >= 0; shift -= 8){
            hist[tid] = 0u; __syncthreads();
            for (int i = tid; i < cnt; i += 256){
                unsigned int u = ssig[i];
                if (shift == 24 || (u >> (shift + 8)) == prefix)
                    atomicAdd(&hist[(u >> shift) & 0xFFu], 1u);
            }
            __syncthreads();
            if (tid == 0){
                int cum = 0, bin = 255;
                for (; bin >= 0; bin--){ cum += (int)hist[bin]; if (cum >= remaining) break; }
                s_bin = bin; s_above = cum - (int)hist[bin];
            }
            __syncthreads();
            prefix = (prefix << 8) | (unsigned int)s_bin;
            remaining -= s_above;
            __syncthreads();
        }

        if (tid == 0) s_cnt = 0;
        __syncthreads();
        for (int i = tid; i < cnt; i += 256){
            unsigned int u = ssig[i];
            if (u >= prefix){
                int p = atomicAdd(&s_cnt, 1);
                if (p < COLBUF)
                    keys[p] = ((unsigned long long)u << 32) |
                              (unsigned long long)(~sidx[i]);
            }
        }
        __syncthreads();
        int m = s_cnt;
        if (m <= COLBUF){
            for (int i = tid; i < COLBUF; i += 256) if (i >= m) keys[i] = 0ULL;
            __syncthreads();
            bitonic_desc(keys, COLBUF, tid, 256);
            if (tid < KC){
                unsigned long long key = keys[tid];
                g_tsc [bc*KC + tid] = __uint_as_float((unsigned int)(key >> 32));
                g_tanc[bc*KC + tid] = (int)(~(unsigned int)key);
            }
        } else {
            ok = false;
        }
        __syncthreads();
    }
    if (!ok) topk_fallback(cls, bc, tid);
}

// ---------------- K3: decode boxes + greedy NMS per (b,c) ------------------
__global__ __launch_bounds__(256) void k_nms(const float* __restrict__ bpred,
                                             const float* __restrict__ anch){
    __shared__ float4 sbox[KC];
    __shared__ float  sarea[KC];
    __shared__ unsigned int smask[KC*8];
    __shared__ unsigned int selig[8];
    __shared__ unsigned int skeep[8];
    int bc  = blockIdx.x;
    int tid = threadIdx.x;
    int b   = bc / NC;

    int   a  = g_tanc[bc*KC + tid];
    float sc = g_tsc [bc*KC + tid];

    float4 bp = reinterpret_cast<const float4*>(bpred)[(size_t)b*NA + a];
    float4 an = reinterpret_cast<const float4*>(anch)[a];

    float dx = mulrn(bp.x, 0.1f), dy = mulrn(bp.y, 0.1f);
    float dw = mulrn(bp.z, 0.2f), dh = mulrn(bp.w, 0.2f);
    float cx = addrn(mulrn(dx, an.z), an.x);
    float cy = addrn(mulrn(dy, an.w), an.y);
    float w  = mulrn(expf(dw), an.z);
    float h  = mulrn(expf(dh), an.w);
    float4 box;
    box.x = subrn(cx, mulrn(0.5f, w));
    box.y = subrn(cy, mulrn(0.5f, h));
    box.z = addrn(cx, mulrn(0.5f, w));
    box.w = addrn(cy, mulrn(0.5f, h));
    sbox[tid]  = box;
    sarea[tid] = mulrn(subrn(box.z, box.x), subrn(box.w, box.y));
    g_box4[bc*KC + tid] = box;

    #pragma unroll
    for (int w8 = 0; w8 < 8; w8++) smask[tid*8 + w8] = 0u;

    unsigned int bal = __ballot_sync(0xFFFFFFFFu, sc > 0.5f);
    if ((tid & 31) == 0) selig[tid >> 5] = bal;
    __syncthreads();

    // balanced pair enumeration: d=1..127 owned by all t; d=128 owned by t<128
    float a1 = sarea[tid];
    int dmax = (tid < 128) ? 128 : 127;
    for (int d = 1; d <= dmax; d++){
        int j = (tid + d) & 255;
        float4 o   = sbox[j];
        float iw   = fmaxf(subrn(fminf(box.z, o.z), fmaxf(box.x, o.x)), 0.0f);
        float ih   = fmaxf(subrn(fminf(box.w, o.w), fmaxf(box.y, o.y)), 0.0f);
        float inter= mulrn(iw, ih);
        if (inter > 0.0f){
            float un = fmaxf(subrn(addrn(a1, sarea[j]), inter), 1e-8f);
            if (__fdiv_rn(inter, un) > 0.5f){
                int lo = tid < j ? tid : j;
                int hi = tid < j ? j : tid;
                atomicOr(&smask[lo*8 + (hi >> 5)], 1u << (hi & 31));
            }
        }
    }
    __syncthreads();

    if (tid == 0){
        unsigned int keep[8];
        #pragma unroll
        for (int w8 = 0; w8 < 8; w8++) keep[w8] = selig[w8];
        for (int i = 0; i < KC; i++){
            if ((keep[i >> 5] >> (i & 31)) & 1u){
                const unsigned int* mi = &smask[i*8];
                #pragma unroll
                for (int w8 = 0; w8 < 8; w8++) keep[w8] &= ~mi[w8];
            }
        }
        int cnt = 0;
        #pragma unroll
        for (int w8 = 0; w8 < 8; w8++){
            unsigned int kk = keep[w8];
            if (cnt >= MAXT){ kk = 0u; }
            else {
                int pc = __popc(kk);
                if (cnt + pc > MAXT){
                    int need = MAXT - cnt;
                    unsigned int outw = 0u;
                    for (int bit = 0; bit < 32 && need > 0; bit++){
                        if ((kk >> bit) & 1u){ outw |= 1u << bit; need--; }
                    }
                    kk = outw;
                }
            }
            cnt += __popc(kk);
            skeep[w8] = kk;
        }
    }
    __syncthreads();
    unsigned int kw = skeep[tid >> 5];
    g_sel[bc*KC + tid] = ((kw >> (tid & 31)) & 1u) ? sc : -1.0f;
}

// ---------------- K4: per-batch global top-200 + output --------------------
__device__ __forceinline__ unsigned int flip_bits(unsigned int u){
    return u ^ ((u >> 31) ? 0xFFFFFFFFu : 0x80000000u);
}

__global__ void k_final(float* __restrict__ out){
    __shared__ unsigned int hist[256];
    __shared__ unsigned long long list[512];
    __shared__ int s_cnt;
    __shared__ int s_bin, s_above;
    int b   = blockIdx.x;
    int tid = threadIdx.x;
    const float* sel = g_sel + b*NFLAT;

    unsigned int prefix = 0;
    int remaining = MAXT;
    for (int shift = 24; shift >= 0; shift -= 8){
        hist[tid] = 0u;
        __syncthreads();
        for (int i = tid; i < NFLAT; i += 256){
            unsigned int fk = flip_bits(__float_as_uint(sel[i]));
            bool match = (shift == 24) || ((fk >> (shift + 8)) == prefix);
            if (match) atomicAdd(&hist[(fk >> shift) & 0xFFu], 1u);
        }
        __syncthreads();
        if (tid == 0){
            int cum = 0, bin = 255;
            for (; bin >= 0; bin--){
                cum += (int)hist[bin];
                if (cum >= remaining) break;
            }
            s_bin = bin;
            s_above = cum - (int)hist[bin];
        }
        __syncthreads();
        prefix = (prefix << 8) | (unsigned int)s_bin;
        remaining -= s_above;
        __syncthreads();
    }

    if (tid == 0) s_cnt = 0;
    __syncthreads();
    for (int i = tid; i < NFLAT; i += 256){
        unsigned int fk = flip_bits(__float_as_uint(sel[i]));
        if (fk >= prefix){
            int pos = atomicAdd(&s_cnt, 1);
            if (pos < 512)
                list[pos] = ((unsigned long long)fk << 32) |
                            (unsigned long long)(~(unsigned int)i);
        }
    }
    __syncthreads();
    int m = s_cnt < 512 ? s_cnt : 512;
    for (int i = tid; i < 512; i += 256) if (i >= m) list[i] = 0ULL;
    __syncthreads();
    bitonic_desc(list, 512, tid, 256);

    if (tid < MAXT){
        unsigned long long key = list[tid];
        unsigned int fk = (unsigned int)(key >> 32);
        unsigned int u  = (fk & 0x80000000u) ? (fk ^ 0x80000000u) : ~fk;
        float scv = __uint_as_float(u);
        int flat  = (int)(~(unsigned int)key);

        float4 bx = make_float4(0.f, 0.f, 0.f, 0.f);
        float  so = 0.f, lab = -1.f;
        if (scv > 0.0f && flat >= 0 && flat < NFLAT){
            int c    = flat >> 8;
            int slot = flat & 255;
            bx  = g_box4[(b*NC + c)*KC + slot];
            so  = scv;
            lab = (float)c;
        }
        float* ob = out;                       // [B, MAXT, 4]
        float* os = out + BATCH*MAXT*4;        // [B, MAXT]
        float* ol = out + BATCH*MAXT*5;        // [B, MAXT]
        reinterpret_cast<float4*>(ob)[b*MAXT + tid] = bx;
        os[b*MAXT + tid] = so;
        ol[b*MAXT + tid] = lab;
    }
}

// ---------------- launch ----------------------------------------------------
extern "C" void kernel_launch(void* const* d_in, const int* in_sizes, int n_in,
                              void* d_out, int out_size){
    const float* box_pred = (const float*)d_in[0];   // [B, A, 4]
    const float* cls_pred = (const float*)d_in[1];   // [B, A, C]
    const float* anchors  = (const float*)d_in[2];   // [A, 4]
    float* out = (float*)d_out;

    k_zero<<<(BC + 255)/256, 256>>>();
    k_filter<<<BATCH*BPB, FBLK>>>(cls_pred);
    k_topk<<<BC, 256>>>(cls_pred);
    k_nms<<<BC, 256>>>(box_pred, anchors);
    k_final<<<BATCH, 256>>>(out);
}

// round 4
// speedup vs baseline: 4.5548x; 1.2968x over previous
#include <cuda_runtime.h>

#define BATCH 8
#define NA 76725
#define NC 80
#define KC 256
#define CAP 4096
#define MAXT 200
#define BC (BATCH*NC)        // 640
#define NFLAT (NC*KC)        // 20480
#define TFILT 2.0f
#define COLBUF 1024

// k_filter tiling
#define FBLK 256
#define F4PT 24
#define CHUNK (FBLK*F4PT)            // 6144 float4 per block
#define N4B (NA*NC/4)                // 1,534,500 float4 per batch
#define BPB ((N4B + CHUNK - 1)/CHUNK) // 250
#define STAGE 2048

// ---------------- scratch (device globals; no allocations) ----------------
__device__ int    g_cnt[BC];
__device__ unsigned long long g_cand[(size_t)BC*CAP]; // (logit_bits<<32)|anchor
__device__ float  g_tsc [BC*KC];     // fallback only
__device__ int    g_tanc[BC*KC];     // fallback only
__device__ float  g_sel [BC*KC];     // kept ? sigmoid : -1
__device__ float4 g_box4[BC*KC];     // decoded corners

// ---------------- exact-rounding helpers ----------------------------------
__device__ __forceinline__ float mulrn(float a, float b){ return __fmul_rn(a,b); }
__device__ __forceinline__ float addrn(float a, float b){ return __fadd_rn(a,b); }
__device__ __forceinline__ float subrn(float a, float b){ return __fsub_rn(a,b); }

// XLA f32 tanh rational approximation, no FMA fusion.
__device__ __forceinline__ float xla_tanh(float x){
    float ax = fabsf(x);
    if (ax < 0.0004f) return x;
    float cx = fminf(fmaxf(x, -7.90531110763549805f), 7.90531110763549805f);
    float s = mulrn(cx, cx);
    float p = -2.76076847742355e-16f;
    p = addrn(mulrn(p, s),  2.00018790482477e-13f);
    p = addrn(mulrn(p, s), -8.60467152213735e-11f);
    p = addrn(mulrn(p, s),  5.12229709037114e-08f);
    p = addrn(mulrn(p, s),  1.48572235717979e-05f);
    p = addrn(mulrn(p, s),  6.37261928875436e-04f);
    p = addrn(mulrn(p, s),  4.89352455891786e-03f);
    p = mulrn(cx, p);
    float q = 1.19825839466702e-06f;
    q = addrn(mulrn(q, s), 1.18534705686654e-04f);
    q = addrn(mulrn(q, s), 2.26843463243900e-03f);
    q = addrn(mulrn(q, s), 4.89352518554385e-03f);
    return __fdiv_rn(p, q);
}
__device__ __forceinline__ float xla_sigmoid(float x){
    return addrn(0.5f, mulrn(0.5f, xla_tanh(mulrn(0.5f, x))));
}

__device__ __forceinline__ unsigned long long pack_key(float sig, unsigned int idx){
    return ((unsigned long long)__float_as_uint(sig) << 32) |
           (unsigned long long)(~idx);
}

// ---------------- K0: zero per-class counters ------------------------------
__global__ void k_zero(){
    int i = blockIdx.x*blockDim.x + threadIdx.x;
    if (i < BC) g_cnt[i] = 0;
}

// ---------------- K1: block-aggregated streaming filter --------------------
__global__ __launch_bounds__(FBLK) void k_filter(const float* __restrict__ cls){
    __shared__ unsigned long long stage[STAGE];
    __shared__ int shist[NC];
    __shared__ int sbase[NC];
    __shared__ int scur [NC];
    __shared__ int scnt;
    int tid   = threadIdx.x;
    int b     = blockIdx.x / BPB;
    int chunk = blockIdx.x % BPB;

    for (int i = tid; i < NC; i += FBLK){ shist[i] = 0; scur[i] = 0; }
    if (tid == 0) scnt = 0;
    __syncthreads();

    const float4* src = reinterpret_cast<const float4*>(cls) + (size_t)b*N4B;
    int base4 = chunk*CHUNK + tid;

    #pragma unroll
    for (int half = 0; half < 3; half++){
        float4 r[8];
        #pragma unroll
        for (int k = 0; k < 8; k++){
            int i4 = base4 + (half*8 + k)*FBLK;
            if (i4 < N4B) r[k] = src[i4];
            else          r[k] = make_float4(-1e30f,-1e30f,-1e30f,-1e30f);
        }
        #pragma unroll
        for (int k = 0; k < 8; k++){
            int i4 = base4 + (half*8 + k)*FBLK;
            int e  = i4*4;
            int a  = e / NC;
            int c0 = e - a*NC;            // multiple of 4
            float vals[4] = {r[k].x, r[k].y, r[k].z, r[k].w};
            #pragma unroll
            for (int t = 0; t < 4; t++){
                if (vals[t] > TFILT){
                    int c = c0 + t;
                    int p = atomicAdd(&scnt, 1);
                    unsigned long long pk =
                        ((unsigned long long)__float_as_uint(vals[t]) << 32) |
                        ((unsigned long long)(unsigned)a << 7) | (unsigned)c;
                    if (p < STAGE){
                        stage[p] = pk;
                        atomicAdd(&shist[c], 1);
                    } else {
                        int bc  = b*NC + c;
                        int pos = atomicAdd(&g_cnt[bc], 1);
                        if (pos < CAP)
                            g_cand[(size_t)bc*CAP + pos] =
                                ((unsigned long long)__float_as_uint(vals[t]) << 32) |
                                (unsigned)a;
                    }
                }
            }
        }
    }
    __syncthreads();

    if (tid < NC){
        int n = shist[tid];
        if (n > 0) sbase[tid] = atomicAdd(&g_cnt[b*NC + tid], n);
    }
    __syncthreads();

    int m = scnt < STAGE ? scnt : STAGE;
    for (int i = tid; i < m; i += FBLK){
        unsigned long long s = stage[i];
        int c = (int)(s & 127u);
        unsigned int a = (unsigned int)((s >> 7) & 0x1FFFFu);
        unsigned int vb = (unsigned int)(s >> 32);
        int off = sbase[c] + atomicAdd(&scur[c], 1);
        if (off < CAP)
            g_cand[(size_t)(b*NC + c)*CAP + off] =
                ((unsigned long long)vb << 32) | a;
    }
}

// ---------------- bitonic sort (descending) on shared u64 ------------------
__device__ __forceinline__ void bitonic_desc(unsigned long long* sk, int n, int tid, int bs){
    for (int k = 2; k <= n; k <<= 1){
        for (int j = k >> 1; j > 0; j >>= 1){
            for (int i = tid; i < n; i += bs){
                int ixj = i ^ j;
                if (ixj > i){
                    unsigned long long x = sk[i], y = sk[ixj];
                    bool swap = ((i & k) == 0) ? (x < y) : (x > y);
                    if (swap){ sk[i] = y; sk[ixj] = x; }
                }
            }
            __syncthreads();
        }
    }
}

// ---------------- K2+K3 fused: top-256 select + decode + NMS ---------------
__global__ __launch_bounds__(256) void k_select(const float* __restrict__ cls,
                                                const float* __restrict__ bpred,
                                                const float* __restrict__ anch){
    __shared__ __align__(16) unsigned int ssig[CAP];  // 16KB; phase2: sbox+sarea
    __shared__ unsigned int sidx[CAP];                // 16KB; phase2: smask
    __shared__ unsigned long long keys[COLBUF];       // 8KB; fallback: red buf
    __shared__ unsigned int hist[256];
    __shared__ unsigned int rscan[256];
    __shared__ int s_bin, s_above, s_cnt;
    __shared__ unsigned int selig[8], skeep[8], sflag[8];

    int bc  = blockIdx.x;
    int tid = threadIdx.x;
    int b   = bc / NC;
    int cnt = g_cnt[bc];

    float sc; int a;
    bool ok = (cnt >= KC && cnt <= CAP);
    if (ok){
        // ---- load candidates, sigmoid once ----
        for (int i = tid; i < cnt; i += 256){
            unsigned long long cd = g_cand[(size_t)bc*CAP + i];
            float sg = xla_sigmoid(__uint_as_float((unsigned int)(cd >> 32)));
            ssig[i] = __float_as_uint(sg);
            sidx[i] = (unsigned int)(cd & 0xFFFFFFFFu);
        }
        __syncthreads();

        // ---- radix-select rank-KC value (descending), parallel bin scan ----
        unsigned int prefix = 0; int remaining = KC;
        for (int shift = 24; shift >= 0; shift -= 8){
            hist[tid] = 0u; __syncthreads();
            for (int i = tid; i < cnt; i += 256){
                unsigned int u = ssig[i];
                if (shift == 24 || (u >> (shift + 8)) == prefix)
                    atomicAdd(&hist[(u >> shift) & 0xFFu], 1u);
            }
            __syncthreads();
            rscan[tid] = hist[tid];
            __syncthreads();
            #pragma unroll
            for (int off = 1; off < 256; off <<= 1){
                unsigned int add = (tid + off < 256) ? rscan[tid + off] : 0u;
                __syncthreads();
                rscan[tid] += add;
                __syncthreads();
            }
            // rscan[i] = count of values with bin >= i
            if ((int)rscan[tid] >= remaining &&
                (tid == 255 || (int)rscan[tid+1] < remaining)){
                s_bin = tid;
                s_above = (tid == 255) ? 0 : (int)rscan[tid+1];
            }
            __syncthreads();
            prefix = (prefix << 8) | (unsigned int)s_bin;
            remaining -= s_above;
            __syncthreads();
        }

        // ---- collect >= threshold ----
        if (tid == 0) s_cnt = 0;
        __syncthreads();
        for (int i = tid; i < cnt; i += 256){
            unsigned int u = ssig[i];
            if (u >= prefix){
                int p = atomicAdd(&s_cnt, 1);
                if (p < COLBUF)
                    keys[p] = ((unsigned long long)u << 32) |
                              (unsigned long long)(~sidx[i]);
            }
        }
        __syncthreads();
        int m = s_cnt;
        if (m <= COLBUF){
            int n = (m <= 512) ? 512 : COLBUF;
            for (int i = tid; i < n; i += 256) if (i >= m) keys[i] = 0ULL;
            __syncthreads();
            bitonic_desc(keys, n, tid, 256);
            unsigned long long key = keys[tid];
            sc = __uint_as_float((unsigned int)(key >> 32));
            a  = (int)(~(unsigned int)key);
        } else {
            ok = false;
        }
        __syncthreads();
    }
    if (!ok){
        // exact fallback: iterative max-extraction over the full logit column
        int bb = bc / NC, c = bc - bb*NC;
        const float* col = cls + (size_t)bb*NA*NC + c;
        unsigned long long* red = keys;
        unsigned long long cur = 0xFFFFFFFFFFFFFFFFULL;
        for (int r = 0; r < KC; r++){
            unsigned long long best = 0ULL;
            for (int ai = tid; ai < NA; ai += 256){
                float sg = xla_sigmoid(col[(size_t)ai*NC]);
                unsigned long long key = pack_key(sg, (unsigned int)ai);
                if (key < cur && key > best) best = key;
            }
            red[tid] = best; __syncthreads();
            for (int s = 128; s > 0; s >>= 1){
                if (tid < s && red[tid+s] > red[tid]) red[tid] = red[tid+s];
                __syncthreads();
            }
            cur = red[0];
            if (tid == 0){
                g_tsc [bc*KC + r] = __uint_as_float((unsigned int)(cur >> 32));
                g_tanc[bc*KC + r] = (int)(~(unsigned int)cur);
            }
            __syncthreads();
        }
        sc = g_tsc [bc*KC + tid];
        a  = g_tanc[bc*KC + tid];
        __syncthreads();
    }

    // =========== phase 2: decode + NMS (reuse ssig/sidx regions) ===========
    float4*       sbox  = reinterpret_cast<float4*>(ssig);         // 4KB
    float*        sarea = reinterpret_cast<float*>(ssig + 1024);   // 1KB
    unsigned int* smask = sidx;                                    // 8KB

    float4 bp = reinterpret_cast<const float4*>(bpred)[(size_t)b*NA + a];
    float4 an = reinterpret_cast<const float4*>(anch)[a];

    float dx = mulrn(bp.x, 0.1f), dy = mulrn(bp.y, 0.1f);
    float dw = mulrn(bp.z, 0.2f), dh = mulrn(bp.w, 0.2f);
    float cx = addrn(mulrn(dx, an.z), an.x);
    float cy = addrn(mulrn(dy, an.w), an.y);
    float w  = mulrn(expf(dw), an.z);
    float h  = mulrn(expf(dh), an.w);
    float4 box;
    box.x = subrn(cx, mulrn(0.5f, w));
    box.y = subrn(cy, mulrn(0.5f, h));
    box.z = addrn(cx, mulrn(0.5f, w));
    box.w = addrn(cy, mulrn(0.5f, h));
    sbox[tid]  = box;
    sarea[tid] = mulrn(subrn(box.z, box.x), subrn(box.w, box.y));
    g_box4[bc*KC + tid] = box;

    #pragma unroll
    for (int w8 = 0; w8 < 8; w8++) smask[tid*8 + w8] = 0u;

    unsigned int bal = __ballot_sync(0xFFFFFFFFu, sc > 0.5f);
    if ((tid & 31) == 0) selig[tid >> 5] = bal;
    __syncthreads();

    // balanced pair enumeration: d=1..127 by all t; d=128 by t<128
    float a1 = sarea[tid];
    int dmax = (tid < 128) ? 128 : 127;
    for (int d = 1; d <= dmax; d++){
        int j = (tid + d) & 255;
        float4 o   = sbox[j];
        float iw   = fmaxf(subrn(fminf(box.z, o.z), fmaxf(box.x, o.x)), 0.0f);
        float ih   = fmaxf(subrn(fminf(box.w, o.w), fmaxf(box.y, o.y)), 0.0f);
        float inter= mulrn(iw, ih);
        if (inter > 0.0f){
            float un = fmaxf(subrn(addrn(a1, sarea[j]), inter), 1e-8f);
            if (__fdiv_rn(inter, un) > 0.5f){
                int lo = tid < j ? tid : j;
                int hi = tid < j ? j : tid;
                atomicOr(&smask[lo*8 + (hi >> 5)], 1u << (hi & 31));
            }
        }
    }
    __syncthreads();

    // row flags: does row tid suppress anything?
    unsigned int rowOr = 0;
    #pragma unroll
    for (int w8 = 0; w8 < 8; w8++) rowOr |= smask[tid*8 + w8];
    unsigned int fb = __ballot_sync(0xFFFFFFFFu, rowOr != 0u);
    if ((tid & 31) == 0) sflag[tid >> 5] = fb;
    __syncthreads();

    if (tid == 0){
        unsigned int keep[8], flg[8];
        #pragma unroll
        for (int w8 = 0; w8 < 8; w8++){ keep[w8] = selig[w8]; flg[w8] = sflag[w8]; }
        for (int i = 0; i < KC; i++){
            unsigned int bit = 1u << (i & 31);
            if (keep[i >> 5] & bit){
                if (flg[i >> 5] & bit){
                    const unsigned int* mi = &smask[i*8];
                    #pragma unroll
                    for (int w8 = 0; w8 < 8; w8++) keep[w8] &= ~mi[w8];
                }
            }
        }
        int kcnt = 0;
        #pragma unroll
        for (int w8 = 0; w8 < 8; w8++){
            unsigned int kk = keep[w8];
            if (kcnt >= MAXT){ kk = 0u; }
            else {
                int pc = __popc(kk);
                if (kcnt + pc > MAXT){
                    int need = MAXT - kcnt;
                    unsigned int outw = 0u;
                    for (int bit = 0; bit < 32 && need > 0; bit++){
                        if ((kk >> bit) & 1u){ outw |= 1u << bit; need--; }
                    }
                    kk = outw;
                }
            }
            kcnt += __popc(kk);
            skeep[w8] = kk;
        }
    }
    __syncthreads();
    unsigned int kw = skeep[tid >> 5];
    g_sel[bc*KC + tid] = ((kw >> (tid & 31)) & 1u) ? sc : -1.0f;
}

// ---------------- K4: per-batch global top-200 + output --------------------
__device__ __forceinline__ unsigned int flip_bits(unsigned int u){
    return u ^ ((u >> 31) ? 0xFFFFFFFFu : 0x80000000u);
}

__global__ __launch_bounds__(256) void k_final(float* __restrict__ out){
    extern __shared__ unsigned int sfk[];          // NFLAT flipped keys (80KB)
    __shared__ unsigned int hist[256];
    __shared__ unsigned int rscan[256];
    __shared__ unsigned long long list[512];
    __shared__ int s_cnt;
    __shared__ int s_bin, s_above;
    int b   = blockIdx.x;
    int tid = threadIdx.x;
    const float4* sel4 = reinterpret_cast<const float4*>(g_sel + b*NFLAT);

    // stage all scores into shared (flipped for descending radix)
    #pragma unroll
    for (int k = 0; k < NFLAT/4/256; k++){
        int i4 = k*256 + tid;
        float4 v = sel4[i4];
        sfk[i4*4 + 0] = flip_bits(__float_as_uint(v.x));
        sfk[i4*4 + 1] = flip_bits(__float_as_uint(v.y));
        sfk[i4*4 + 2] = flip_bits(__float_as_uint(v.z));
        sfk[i4*4 + 3] = flip_bits(__float_as_uint(v.w));
    }
    __syncthreads();

    unsigned int prefix = 0;
    int remaining = MAXT;
    for (int shift = 24; shift >= 0; shift -= 8){
        hist[tid] = 0u;
        __syncthreads();
        for (int i = tid; i < NFLAT; i += 256){
            unsigned int fk = sfk[i];
            if (shift == 24 || (fk >> (shift + 8)) == prefix)
                atomicAdd(&hist[(fk >> shift) & 0xFFu], 1u);
        }
        __syncthreads();
        rscan[tid] = hist[tid];
        __syncthreads();
        #pragma unroll
        for (int off = 1; off < 256; off <<= 1){
            unsigned int add = (tid + off < 256) ? rscan[tid + off] : 0u;
            __syncthreads();
            rscan[tid] += add;
            __syncthreads();
        }
        if ((int)rscan[tid] >= remaining &&
            (tid == 255 || (int)rscan[tid+1] < remaining)){
            s_bin = tid;
            s_above = (tid == 255) ? 0 : (int)rscan[tid+1];
        }
        __syncthreads();
        prefix = (prefix << 8) | (unsigned int)s_bin;
        remaining -= s_above;
        __syncthreads();
    }

    if (tid == 0) s_cnt = 0;
    __syncthreads();
    for (int i = tid; i < NFLAT; i += 256){
        unsigned int fk = sfk[i];
        if (fk >= prefix){
            int pos = atomicAdd(&s_cnt, 1);
            if (pos < 512)
                list[pos] = ((unsigned long long)fk << 32) |
                            (unsigned long long)(~(unsigned int)i);
        }
    }
    __syncthreads();
    int m = s_cnt < 512 ? s_cnt : 512;
    for (int i = tid; i < 512; i += 256) if (i >= m) list[i] = 0ULL;
    __syncthreads();
    bitonic_desc(list, 512, tid, 256);

    if (tid < MAXT){
        unsigned long long key = list[tid];
        unsigned int fk = (unsigned int)(key >> 32);
        unsigned int u  = (fk & 0x80000000u) ? (fk ^ 0x80000000u) : ~fk;
        float scv = __uint_as_float(u);
        int flat  = (int)(~(unsigned int)key);

        float4 bx = make_float4(0.f, 0.f, 0.f, 0.f);
        float  so = 0.f, lab = -1.f;
        if (scv > 0.0f && flat >= 0 && flat < NFLAT){
            int c    = flat >> 8;
            int slot = flat & 255;
            bx  = g_box4[(b*NC + c)*KC + slot];
            so  = scv;
            lab = (float)c;
        }
        float* ob = out;                       // [B, MAXT, 4]
        float* os = out + BATCH*MAXT*4;        // [B, MAXT]
        float* ol = out + BATCH*MAXT*5;        // [B, MAXT]
        reinterpret_cast<float4*>(ob)[b*MAXT + tid] = bx;
        os[b*MAXT + tid] = so;
        ol[b*MAXT + tid] = lab;
    }
}

// ---------------- launch ----------------------------------------------------
extern "C" void kernel_launch(void* const* d_in, const int* in_sizes, int n_in,
                              void* d_out, int out_size){
    const float* box_pred = (const float*)d_in[0];   // [B, A, 4]
    const float* cls_pred = (const float*)d_in[1];   // [B, A, C]
    const float* anchors  = (const float*)d_in[2];   // [A, 4]
    float* out = (float*)d_out;

    cudaFuncSetAttribute(k_final, cudaFuncAttributeMaxDynamicSharedMemorySize,
                         NFLAT*sizeof(unsigned int));

    k_zero<<<(BC + 255)/256, 256>>>();
    k_filter<<<BATCH*BPB, FBLK>>>(cls_pred);
    k_select<<<BC, 256>>>(cls_pred, box_pred, anchors);
    k_final<<<BATCH, 256, NFLAT*sizeof(unsigned int)>>>(out);
}